// round 1
// baseline (speedup 1.0000x reference)
#include <cuda_runtime.h>

#define Nn   2048
#define IND  128
#define HIDD 64
#define Ee   32768
#define EPSf 1e-5f

// -------- scratch (device globals; no allocation allowed) --------
__device__ __align__(256) float g_p1[Nn * HIDD * HIDD];   // relu(h@W1+b1), [N, 64*64]
__device__ __align__(256) float g_p2[Nn * HIDD];          // relu(h@Wp2+bp2)
__device__ int g_cnt[Nn];
__device__ int g_off[Nn + 1];
__device__ int g_cur[Nn];
__device__ int g_eidx[Ee];

// ================= edge bucketing by src =================
__global__ void k_zero() {
    int i = blockIdx.x * blockDim.x + threadIdx.x;
    if (i < Nn) g_cnt[i] = 0;
}

__global__ void k_hist(const int* __restrict__ src) {
    int e = blockIdx.x * blockDim.x + threadIdx.x;
    if (e < Ee) atomicAdd(&g_cnt[src[e]], 1);
}

__global__ void k_scan() {
    __shared__ int part[256];
    int t = threadIdx.x;
    int base = t * 8;
    int loc[8];
    int s = 0;
#pragma unroll
    for (int i = 0; i < 8; i++) { loc[i] = g_cnt[base + i]; s += loc[i]; }
    part[t] = s;
    __syncthreads();
    if (t == 0) {
        int run = 0;
        for (int i = 0; i < 256; i++) { int v = part[i]; part[i] = run; run += v; }
    }
    __syncthreads();
    int run = part[t];
#pragma unroll
    for (int i = 0; i < 8; i++) {
        g_off[base + i] = run;
        g_cur[base + i] = run;
        run += loc[i];
    }
    if (t == 255) g_off[Nn] = run;
}

__global__ void k_scatter(const int* __restrict__ src) {
    int e = blockIdx.x * blockDim.x + threadIdx.x;
    if (e < Ee) {
        int s = src[e];
        int p = atomicAdd(&g_cur[s], 1);
        g_eidx[p] = e;
    }
}

// ================= p1 = relu(h @ W1 + b1)  [2048x4096, K=128] =================
#define BM 64
#define BN 64
#define BK 32
__global__ __launch_bounds__(256) void k_p1gemm(const float* __restrict__ h,
                                                const float* __restrict__ W1,
                                                const float* __restrict__ b1) {
    __shared__ float As[BK][BM + 1];              // transposed, padded
    __shared__ __align__(16) float Bs[BK][BN];
    int tid = threadIdx.x;
    int tx = tid & 15, ty = tid >> 4;
    int row0 = blockIdx.y * BM;
    int col0 = blockIdx.x * BN;

    float acc[4][4];
#pragma unroll
    for (int m = 0; m < 4; m++)
#pragma unroll
        for (int n = 0; n < 4; n++) acc[m][n] = 0.f;

    for (int k0 = 0; k0 < IND; k0 += BK) {
        {
            int r = tid >> 3;            // 0..31
            int c = (tid & 7) * 4;       // 0..28
#pragma unroll
            for (int rr = 0; rr < BM; rr += 32) {
                float4 v = *(const float4*)&h[(row0 + r + rr) * IND + k0 + c];
                As[c + 0][r + rr] = v.x;
                As[c + 1][r + rr] = v.y;
                As[c + 2][r + rr] = v.z;
                As[c + 3][r + rr] = v.w;
            }
        }
        {
            int r = tid >> 4;            // 0..15
            int c = (tid & 15) * 4;      // 0..60
#pragma unroll
            for (int rr = 0; rr < BK; rr += 16) {
                *(float4*)&Bs[r + rr][c] =
                    *(const float4*)&W1[(k0 + r + rr) * (HIDD * HIDD) + col0 + c];
            }
        }
        __syncthreads();
#pragma unroll
        for (int kk = 0; kk < BK; kk++) {
            float a0 = As[kk][ty * 4 + 0];
            float a1 = As[kk][ty * 4 + 1];
            float a2 = As[kk][ty * 4 + 2];
            float a3 = As[kk][ty * 4 + 3];
            float4 bv = *(const float4*)&Bs[kk][tx * 4];
            acc[0][0] += a0 * bv.x; acc[0][1] += a0 * bv.y; acc[0][2] += a0 * bv.z; acc[0][3] += a0 * bv.w;
            acc[1][0] += a1 * bv.x; acc[1][1] += a1 * bv.y; acc[1][2] += a1 * bv.z; acc[1][3] += a1 * bv.w;
            acc[2][0] += a2 * bv.x; acc[2][1] += a2 * bv.y; acc[2][2] += a2 * bv.z; acc[2][3] += a2 * bv.w;
            acc[3][0] += a3 * bv.x; acc[3][1] += a3 * bv.y; acc[3][2] += a3 * bv.z; acc[3][3] += a3 * bv.w;
        }
        __syncthreads();
    }
    int col = col0 + tx * 4;
    float4 bb = *(const float4*)&b1[col];
#pragma unroll
    for (int m = 0; m < 4; m++) {
        int row = row0 + ty * 4 + m;
        float4 o;
        o.x = fmaxf(acc[m][0] + bb.x, 0.f);
        o.y = fmaxf(acc[m][1] + bb.y, 0.f);
        o.z = fmaxf(acc[m][2] + bb.z, 0.f);
        o.w = fmaxf(acc[m][3] + bb.w, 0.f);
        *(float4*)&g_p1[row * (HIDD * HIDD) + col] = o;
    }
}

// ================= p2 = relu(h @ Wp2 + bp2) =================
__global__ void k_p2(const float* __restrict__ h,
                     const float* __restrict__ Wp2,
                     const float* __restrict__ bp2) {
    __shared__ float hs[IND];
    int row = blockIdx.x;
    int j = threadIdx.x;
    hs[j] = h[row * IND + j];
    hs[j + 64] = h[row * IND + j + 64];
    __syncthreads();
    float acc = bp2[j];
#pragma unroll 8
    for (int k = 0; k < IND; k++) acc += hs[k] * Wp2[k * HIDD + j];
    g_p2[row * HIDD + j] = fmaxf(acc, 0.f);
}

// ================= local branch: out = relu(bnL(relu(conv(LN))@W2+b2)) + e =================
__global__ __launch_bounds__(128) void k_local(const float* __restrict__ local,
                                               const float* __restrict__ ein,
                                               const int* __restrict__ src,
                                               const int* __restrict__ dst,
                                               const float* __restrict__ ln_w,
                                               const float* __restrict__ ln_b,
                                               const float* __restrict__ conv_w,
                                               const float* __restrict__ conv_b,
                                               const float* __restrict__ W2,
                                               const float* __restrict__ b2,
                                               const float* __restrict__ bnL_g,
                                               const float* __restrict__ bnL_b,
                                               float* __restrict__ out) {
    __shared__ float W2s[IND * HIDD];
    __shared__ float Tsm[8][IND];
    __shared__ float sa[IND + 2], sb[IND + 2];
    __shared__ float4 red[4];

    int t = threadIdx.x;
    for (int i = t; i < IND * HIDD; i += 128) W2s[i] = W2[i];
    float lw = ln_w[t], lb = ln_b[t];
    float cw0 = conv_w[0], cw1 = conv_w[1], cw2 = conv_w[2];
    float cw3 = conv_w[3], cw4 = conv_w[4], cw5 = conv_w[5];
    float cb = conv_b[0];
    int e0 = blockIdx.x * 8;
    int lane = t & 31, warp = t >> 5;
    if (t == 0) { sa[0] = 0.f; sa[IND + 1] = 0.f; sb[0] = 0.f; sb[IND + 1] = 0.f; }

    for (int eo = 0; eo < 8; eo++) {
        int e = e0 + eo;
        int s = src[e], dd = dst[e];
        float a = local[s * IND + t];
        float b = local[dd * IND + t];
        float4 v = make_float4(a, a * a, b, b * b);
#pragma unroll
        for (int o = 16; o; o >>= 1) {
            v.x += __shfl_down_sync(0xffffffffu, v.x, o);
            v.y += __shfl_down_sync(0xffffffffu, v.y, o);
            v.z += __shfl_down_sync(0xffffffffu, v.z, o);
            v.w += __shfl_down_sync(0xffffffffu, v.w, o);
        }
        if (lane == 0) red[warp] = v;
        __syncthreads();
        float4 tot = red[0];
        tot.x += red[1].x + red[2].x + red[3].x;
        tot.y += red[1].y + red[2].y + red[3].y;
        tot.z += red[1].z + red[2].z + red[3].z;
        tot.w += red[1].w + red[2].w + red[3].w;
        float mua = tot.x * (1.f / IND), vara = tot.y * (1.f / IND) - mua * mua;
        float mub = tot.z * (1.f / IND), varb = tot.w * (1.f / IND) - mub * mub;
        float an = (a - mua) * rsqrtf(vara + EPSf) * lw + lb;
        float bn_ = (b - mub) * rsqrtf(varb + EPSf) * lw + lb;
        sa[t + 1] = an;
        sb[t + 1] = bn_;
        __syncthreads();
        float c = cw0 * sa[t] + cw1 * sa[t + 1] + cw2 * sa[t + 2]
                + cw3 * sb[t] + cw4 * sb[t + 1] + cw5 * sb[t + 2] + cb;
        Tsm[eo][t] = fmaxf(c, 0.f);
        __syncthreads();
    }

    int j = t & 63, half = t >> 6;
    float c0 = 0.f, c1 = 0.f, c2 = 0.f, c3 = 0.f;
#pragma unroll 4
    for (int i = 0; i < IND; i++) {
        float w = W2s[i * HIDD + j];
        c0 += Tsm[half + 0][i] * w;
        c1 += Tsm[half + 2][i] * w;
        c2 += Tsm[half + 4][i] * w;
        c3 += Tsm[half + 6][i] * w;
    }
    float rs = rsqrtf(1.f + EPSf);
    float sL = bnL_g[j] * rs, bL = bnL_b[j];
    float bb = b2[j];
    float r0 = fmaxf((c0 + bb) * sL + bL, 0.f);
    float r1 = fmaxf((c1 + bb) * sL + bL, 0.f);
    float r2 = fmaxf((c2 + bb) * sL + bL, 0.f);
    float r3 = fmaxf((c3 + bb) * sL + bL, 0.f);
    out[(e0 + half + 0) * HIDD + j] = r0 + ein[(e0 + half + 0) * HIDD + j];
    out[(e0 + half + 2) * HIDD + j] = r1 + ein[(e0 + half + 2) * HIDD + j];
    out[(e0 + half + 4) * HIDD + j] = r2 + ein[(e0 + half + 4) * HIDD + j];
    out[(e0 + half + 6) * HIDD + j] = r3 + ein[(e0 + half + 6) * HIDD + j];
}

// ================= global branch: one block per src node =================
__global__ __launch_bounds__(256) void k_global(const int* __restrict__ dst,
                                                const float* __restrict__ W3,
                                                const float* __restrict__ b3,
                                                const float* __restrict__ bng_g,
                                                const float* __restrict__ bng_b,
                                                const float* __restrict__ bnG_g,
                                                const float* __restrict__ bnG_b,
                                                float* __restrict__ out) {
    __shared__ float p1s[HIDD][HIDD + 1];   // [k][d], padded
    __shared__ float W3s[HIDD * HIDD];
    __shared__ float p2s[4][HIDD];
    __shared__ float zs[4][HIDD];

    int node = blockIdx.x;
    int t = threadIdx.x;
    int beg = g_off[node], end = g_off[node + 1];
    if (beg == end) return;

    const float* p1row = &g_p1[node * (HIDD * HIDD)];
    for (int jdx = t; jdx < HIDD * HIDD; jdx += 256) {
        int d = jdx >> 6, k = jdx & 63;
        p1s[k][d] = p1row[jdx];
    }
    for (int jdx = t; jdx < HIDD * HIDD; jdx += 256) W3s[jdx] = W3[jdx];

    int d = t & 63, g = t >> 6;
    float rs = rsqrtf(1.f + EPSf);
    float s1 = bng_g[d] * rs, o1 = bng_b[d];
    float s2 = bnG_g[d] * rs, o2 = bnG_b[d];
    float b3v = b3[d];
    __syncthreads();

    for (int base = beg; base < end; base += 4) {
        int ei = base + g;
        bool valid = ei < end;
        int e = 0;
        if (valid) {
            e = g_eidx[ei];
            int dn = dst[e];
            p2s[g][d] = g_p2[dn * HIDD + d];
        }
        __syncthreads();
        if (valid) {
            float y = 0.f;
#pragma unroll 8
            for (int k = 0; k < HIDD; k++) y += p1s[k][d] * p2s[g][k];
            zs[g][d] = y * s1 + o1;
        }
        __syncthreads();
        if (valid) {
            float o = b3v;
#pragma unroll 8
            for (int k = 0; k < HIDD; k++) o += zs[g][k] * W3s[k * HIDD + d];
            float v = fmaxf(o * s2 + o2, 0.f);
            out[e * HIDD + d] += v;
        }
        __syncthreads();
    }
}

// ================= launch =================
extern "C" void kernel_launch(void* const* d_in, const int* in_sizes, int n_in,
                              void* d_out, int out_size) {
    const float* h      = (const float*)d_in[0];
    const float* local_ = (const float*)d_in[1];
    const float* ein    = (const float*)d_in[2];
    const int*   src    = (const int*)d_in[3];
    const int*   dst    = (const int*)d_in[4];
    const float* ln_w   = (const float*)d_in[5];
    const float* ln_b   = (const float*)d_in[6];
    const float* conv_w = (const float*)d_in[7];
    const float* conv_b = (const float*)d_in[8];
    const float* W1     = (const float*)d_in[9];
    const float* b1     = (const float*)d_in[10];
    const float* Wp2    = (const float*)d_in[11];
    const float* bp2    = (const float*)d_in[12];
    const float* W2     = (const float*)d_in[13];
    const float* b2     = (const float*)d_in[14];
    const float* W3     = (const float*)d_in[15];
    const float* b3     = (const float*)d_in[16];
    const float* bng_g  = (const float*)d_in[17];
    const float* bng_b  = (const float*)d_in[18];
    const float* bnG_g  = (const float*)d_in[19];
    const float* bnG_b  = (const float*)d_in[20];
    const float* bnL_g  = (const float*)d_in[21];
    const float* bnL_b  = (const float*)d_in[22];
    float* out = (float*)d_out;

    k_zero<<<8, 256>>>();
    k_hist<<<Ee / 256, 256>>>(src);
    k_scan<<<1, 256>>>();
    k_scatter<<<Ee / 256, 256>>>(src);

    k_p1gemm<<<dim3((HIDD * HIDD) / BN, Nn / BM), 256>>>(h, W1, b1);
    k_p2<<<Nn, 64>>>(h, Wp2, bp2);
    k_local<<<Ee / 8, 128>>>(local_, ein, src, dst, ln_w, ln_b, conv_w, conv_b,
                             W2, b2, bnL_g, bnL_b, out);
    k_global<<<Nn, 256>>>(dst, W3, b3, bng_g, bng_b, bnG_g, bnG_b, out);
}